// round 9
// baseline (speedup 1.0000x reference)
#include <cuda_runtime.h>

#define MAXN 100000
#define DD   128

// ---- tiny device globals only (~3.2 MB total) ----
__device__ float g_s4[(size_t)MAXN * 4];   // 1.6 MB scratch (last-slice subcols)
__device__ int   g_deg_s[MAXN];
__device__ int   g_deg_d[MAXN];
__device__ float g_inv_o[MAXN];            // 1/sqrt(max(outdeg,1))
__device__ float g_inv_i[MAXN];            // 1/sqrt(max(indeg,1))

// -------------------------------------------------------------------------
// zero all of d_out + degree counters
__global__ void k_init(float* __restrict__ out, int n4, int n)
{
    int i = blockIdx.x * blockDim.x + threadIdx.x;
    if (i < n4) reinterpret_cast<float4*>(out)[i] = make_float4(0.f,0.f,0.f,0.f);
    if (i < n) { g_deg_s[i] = 0; g_deg_d[i] = 0; }
}

// zero one 16-col region of out
__global__ void k_zreg(float* __restrict__ out, int c0, int n4)
{
    int t = blockIdx.x * blockDim.x + threadIdx.x;
    if (t >= n4) return;
    int node = t >> 2;
    int q    = t & 3;
    reinterpret_cast<float4*>(out + (size_t)node * DD + c0)[q] =
        make_float4(0.f, 0.f, 0.f, 0.f);
}

__global__ void k_deg(const int* __restrict__ src, const int* __restrict__ dst, int E)
{
    int i = blockIdx.x * blockDim.x + threadIdx.x;
    if (i < E) {
        atomicAdd(&g_deg_s[src[i]], 1);
        atomicAdd(&g_deg_d[dst[i]], 1);
    }
}

__global__ void k_norm(int n)
{
    int i = blockIdx.x * blockDim.x + threadIdx.x;
    if (i < n) {
        g_inv_o[i] = rsqrtf((float)max(g_deg_s[i], 1));
        g_inv_i[i] = rsqrtf((float)max(g_deg_d[i], 1));
    }
}

// SpMM over a (4*W4)-column slice: W4 lanes per edge, one float4 each.
// o[dst, oc0:+4*W4] += x[src, xc0:+4*W4] (* inv_o[src] if SCALE)
template <int W4, bool SCALE>
__global__ void k_spmm(const float* __restrict__ x, int xs, int xc0,
                       float* __restrict__ o, int os, int oc0,
                       const int* __restrict__ src, const int* __restrict__ dst,
                       int E)
{
    int t = blockIdx.x * blockDim.x + threadIdx.x;
    int e = t / W4;
    int q = t % W4;
    if (e >= E) return;
    int s = src[e];
    int d = dst[e];
    float4 v = *reinterpret_cast<const float4*>(x + (size_t)s * xs + xc0 + q * 4);
    if (SCALE) {
        float sc = g_inv_o[s];
        v.x *= sc; v.y *= sc; v.z *= sc; v.w *= sc;
    }
    atomicAdd(reinterpret_cast<float4*>(o + (size_t)d * os + oc0 + q * 4), v);
}

// post-layer-0: out[:,c0 slice] = (acc*inv_i + b0)*inv_o in place;
// zero the scratch slice (so SpMM2 can accumulate there).
template <int W4>
__global__ void k_post1(const float* __restrict__ b0, float* __restrict__ out,
                        int c0, float* __restrict__ scr, int ss, int sc0,
                        int total)
{
    int t = blockIdx.x * blockDim.x + threadIdx.x;
    if (t >= total) return;
    int node = t / W4;
    int q    = t % W4;
    float4* p = reinterpret_cast<float4*>(out + (size_t)node * DD + c0) + q;
    float4 v = *p;
    float4 b = reinterpret_cast<const float4*>(b0 + c0)[q];
    float ii = g_inv_i[node];
    float io = g_inv_o[node];
    v.x = (v.x * ii + b.x) * io;
    v.y = (v.y * ii + b.y) * io;
    v.z = (v.z * ii + b.z) * io;
    v.w = (v.w * ii + b.w) * io;
    *p = v;
    reinterpret_cast<float4*>(scr + (size_t)node * ss + sc0)[q] =
        make_float4(0.f, 0.f, 0.f, 0.f);
}

// post-layer-1: scratch *= inv_i in place; zero out[:,c0 slice]
// (so SpMM3 can accumulate the final sum there). GEMM deferred:
// seg((g@W1+b1)[src],dst) == seg(g[src],dst)@W1 + indeg_raw*b1.
template <int W4>
__global__ void k_post2(float* __restrict__ out, int c0,
                        float* __restrict__ scr, int ss, int sc0, int total)
{
    int t = blockIdx.x * blockDim.x + threadIdx.x;
    if (t >= total) return;
    int node = t / W4;
    int q    = t % W4;
    float ii = g_inv_i[node];
    float4* sp = reinterpret_cast<float4*>(scr + (size_t)node * ss + sc0) + q;
    float4 v = *sp;
    v.x *= ii; v.y *= ii; v.z *= ii; v.w *= ii;
    *sp = v;
    reinterpret_cast<float4*>(out + (size_t)node * DD + c0)[q] =
        make_float4(0.f, 0.f, 0.f, 0.f);
}

__device__ __forceinline__ void fma4(float4& c, float s, const float4& v)
{
    c.x += s * v.x; c.y += s * v.y; c.z += s * v.z; c.w += s * v.w;
}

// in-place GEMM: out[r,:] = out[r,:] @ W + indeg_raw[r]*b1.
// 32 rows/block, full 128 cols (in-place safe: rows staged to smem first).
__global__ __launch_bounds__(256)
void k_gemm(const float* __restrict__ W,
            const float* __restrict__ b1,
            float*       __restrict__ out, int n)
{
    __shared__ float As[32 * 128];   // [r][k], 16 KB
    int tid  = threadIdx.x;
    int row0 = blockIdx.x * 32;

    for (int i = tid; i < 32 * 32; i += 256) {
        int r  = i >> 5;
        int kc = i & 31;
        int gr = row0 + r;
        float4 v = (gr < n)
            ? reinterpret_cast<const float4*>(out + (size_t)gr * DD)[kc]
            : make_float4(0.f, 0.f, 0.f, 0.f);
        reinterpret_cast<float4*>(As)[i] = v;
    }
    __syncthreads();

    int r = tid >> 3;       // 0..31
    int q = tid & 7;        // float4-cols {q, q+8, q+16, q+24}

    float4 a0 = make_float4(0.f, 0.f, 0.f, 0.f);
    float4 a1 = a0, a2 = a0, a3 = a0;

    const float4* W4 = reinterpret_cast<const float4*>(W);
    const float*  Ar = As + r * 128;

    #pragma unroll 4
    for (int k = 0; k < 128; k++) {
        float a = Ar[k];
        fma4(a0, a, W4[k * 32 + q]);
        fma4(a1, a, W4[k * 32 + q + 8]);
        fma4(a2, a, W4[k * 32 + q + 16]);
        fma4(a3, a, W4[k * 32 + q + 24]);
    }

    int gr = row0 + r;
    if (gr < n) {
        float dg = (float)g_deg_d[gr];                 // raw in-degree
        const float4* b4 = reinterpret_cast<const float4*>(b1);
        float4* op = reinterpret_cast<float4*>(out + (size_t)gr * DD);
        float4 b, o;
        b = b4[q];      o.x=a0.x+dg*b.x; o.y=a0.y+dg*b.y; o.z=a0.z+dg*b.z; o.w=a0.w+dg*b.w; op[q]      = o;
        b = b4[q + 8];  o.x=a1.x+dg*b.x; o.y=a1.y+dg*b.y; o.z=a1.z+dg*b.z; o.w=a1.w+dg*b.w; op[q + 8]  = o;
        b = b4[q + 16]; o.x=a2.x+dg*b.x; o.y=a2.y+dg*b.y; o.z=a2.z+dg*b.z; o.w=a2.w+dg*b.w; op[q + 16] = o;
        b = b4[q + 24]; o.x=a3.x+dg*b.x; o.y=a3.y+dg*b.y; o.z=a3.z+dg*b.z; o.w=a3.w+dg*b.w; op[q + 24] = o;
    }
}

extern "C" void kernel_launch(void* const* d_in, const int* in_sizes, int n_in,
                              void* d_out, int out_size)
{
    const float* feat = (const float*)d_in[0];
    const int*   src  = (const int*)  d_in[1];
    const int*   dst  = (const int*)  d_in[2];
    const float* W1   = (const float*)d_in[3];
    const float* b0   = (const float*)d_in[4];
    const float* b1   = (const float*)d_in[5];
    float*       out  = (float*)d_out;

    int E = in_sizes[1];
    int N = out_size / DD;
    if (N > MAXN) N = MAXN;

    float* s4 = nullptr;
    cudaGetSymbolAddress((void**)&s4, g_s4);   // pure host query; capture-safe

    dim3 blk(256);
    int n4all = N * (DD / 4);
    int gInit = (n4all + 255) / 256;
    int gE    = (E + 255) / 256;
    int gN    = (N + 255) / 256;
    int gE4   = ((E * 4) + 255) / 256;   // 4 lanes/edge (16-col slices)
    int gE1   = gE;                      // 1 lane/edge  (4-col sub-slices)
    int n4w   = N * 4;                   // work items, 16-col posts
    int gP4   = (n4w + 255) / 256;
    int gP1   = gN;

    k_init<<<gInit, blk>>>(out, n4all, N);
    k_deg<<<gE, blk>>>(src, dst, E);
    k_norm<<<gN, blk>>>(N);

    // slices 0..6: scratch = next 16-col region of out (still zero from init;
    // each region is re-zeroed before serving as its own slice's accumulator)
    for (int s = 0; s < 7; s++) {
        int c0  = s * 16;
        int sc0 = c0 + 16;
        if (s > 0) k_zreg<<<gP4, blk>>>(out, c0, n4w);          // clear old scratch
        k_spmm<4, true><<<gE4, blk>>>(feat, DD, c0, out, DD, c0, src, dst, E);
        k_post1<4><<<gP4, blk>>>(b0, out, c0, out, DD, sc0, n4w);
        k_spmm<4, false><<<gE4, blk>>>(out, DD, c0, out, DD, sc0, src, dst, E);
        k_post2<4><<<gP4, blk>>>(out, c0, out, DD, sc0, n4w);
        k_spmm<4, false><<<gE4, blk>>>(out, DD, sc0, out, DD, c0, src, dst, E);
    }

    // slice 7 (cols 112..127): region currently holds scratch garbage — zero,
    // then process in four 4-col sub-slices through the 1.6 MB global.
    k_zreg<<<gP4, blk>>>(out, 112, n4w);
    for (int t = 0; t < 4; t++) {
        int c = 112 + t * 4;
        k_spmm<1, true><<<gE1, blk>>>(feat, DD, c, out, DD, c, src, dst, E);
        k_post1<1><<<gP1, blk>>>(b0, out, c, s4, 4, 0, N);
        k_spmm<1, false><<<gE1, blk>>>(out, DD, c, s4, 4, 0, src, dst, E);
        k_post2<1><<<gP1, blk>>>(out, c, s4, 4, 0, N);
        k_spmm<1, false><<<gE1, blk>>>(s4, 4, 0, out, DD, c, src, dst, E);
    }

    // in-place: out = out @ W1 + indeg_raw * b1
    int gG = (N + 31) / 32;
    k_gemm<<<gG, blk>>>(W1, b1, out, N);
}

// round 10
// speedup vs baseline: 1.2655x; 1.2655x over previous
#include <cuda_runtime.h>

#define MAXN 100000
#define MAXE 650000
#define DD   128

// ---- device globals (~5.8 MB total) ----
__device__ int   g_deg_s[MAXN];          // out-degree
__device__ int   g_deg_d[MAXN];          // in-degree (CSR row lengths + bias)
__device__ int   g_rowptr[MAXN + 1];
__device__ int   g_cursor[MAXN];
__device__ int   g_csrc[MAXE];           // src node of each edge, grouped by dst
__device__ int   g_bsum[1024];
__device__ float g_s4[(size_t)MAXN * 4]; // 1.6 MB scratch (last-slice subcols)

// -------------------------------------------------------------------------
__global__ void k_init(int n)
{
    int i = blockIdx.x * blockDim.x + threadIdx.x;
    if (i < n) { g_deg_s[i] = 0; g_deg_d[i] = 0; }
}

__global__ void k_deg(const int* __restrict__ src, const int* __restrict__ dst, int E)
{
    int i = blockIdx.x * blockDim.x + threadIdx.x;
    if (i < E) {
        atomicAdd(&g_deg_s[src[i]], 1);
        atomicAdd(&g_deg_d[dst[i]], 1);
    }
}

// exclusive scan of g_deg_d -> g_rowptr, 1024/block + block sums
__global__ void k_scan1(int n)
{
    __shared__ int s[1024];
    int t = threadIdx.x;
    int i = blockIdx.x * 1024 + t;
    int v = (i < n) ? g_deg_d[i] : 0;
    s[t] = v;
    __syncthreads();
    for (int off = 1; off < 1024; off <<= 1) {
        int x = (t >= off) ? s[t - off] : 0;
        __syncthreads();
        s[t] += x;
        __syncthreads();
    }
    if (i < n) g_rowptr[i] = s[t] - v;     // block-local exclusive
    if (t == 1023) g_bsum[blockIdx.x] = s[1023];
}

// serial scan of block sums (nb <= 1024; trivial work)
__global__ void k_scan2(int nb)
{
    if (threadIdx.x == 0 && blockIdx.x == 0) {
        int run = 0;
        for (int b = 0; b < nb; b++) { int x = g_bsum[b]; g_bsum[b] = run; run += x; }
    }
}

__global__ void k_scan3(int n, int E)
{
    int i = blockIdx.x * blockDim.x + threadIdx.x;
    if (i < n) {
        int r = g_rowptr[i] + g_bsum[i >> 10];
        g_rowptr[i] = r;
        g_cursor[i] = r;
    }
    if (i == 0) g_rowptr[n] = E;
}

__global__ void k_fill(const int* __restrict__ src, const int* __restrict__ dst, int E)
{
    int e = blockIdx.x * blockDim.x + threadIdx.x;
    if (e < E) {
        int pos = atomicAdd(&g_cursor[dst[e]], 1);
        g_csrc[pos] = src[e];
    }
}

// -------------------------------------------------------------------------
// Pull-CSR SpMM with fused epilogue. W4 float4-columns per node, one thread
// per (node, float4-col). MODE 0: layer0 (src scale inv_o; epi (v*ii+b0)*io)
//                          MODE 1: layer1 aggregate (epi v*ii)
//                          MODE 2: final neighbor sum (epi v)
template <int W4, int MODE>
__global__ void k_csr(const float* __restrict__ x, int xs, int xc0,
                      float* __restrict__ o, int os, int oc0,
                      const float* __restrict__ b0, int n)
{
    int t = blockIdx.x * blockDim.x + threadIdx.x;
    int node = t / W4;
    int q    = t % W4;
    if (node >= n) return;

    int beg = g_rowptr[node];
    int end = g_rowptr[node + 1];

    float4 acc = make_float4(0.f, 0.f, 0.f, 0.f);
    for (int j = beg; j < end; j++) {
        int s = g_csrc[j];
        float4 v = *reinterpret_cast<const float4*>(x + (size_t)s * xs + xc0 + q * 4);
        if (MODE == 0) {
            float sc = rsqrtf((float)max(g_deg_s[s], 1));
            acc.x += v.x * sc; acc.y += v.y * sc;
            acc.z += v.z * sc; acc.w += v.w * sc;
        } else {
            acc.x += v.x; acc.y += v.y; acc.z += v.z; acc.w += v.w;
        }
    }

    if (MODE == 0) {
        float ii = rsqrtf((float)max(g_deg_d[node], 1));
        float io = rsqrtf((float)max(g_deg_s[node], 1));
        float4 b = reinterpret_cast<const float4*>(b0 + xc0)[q];
        acc.x = (acc.x * ii + b.x) * io;
        acc.y = (acc.y * ii + b.y) * io;
        acc.z = (acc.z * ii + b.z) * io;
        acc.w = (acc.w * ii + b.w) * io;
    } else if (MODE == 1) {
        float ii = rsqrtf((float)max(g_deg_d[node], 1));
        acc.x *= ii; acc.y *= ii; acc.z *= ii; acc.w *= ii;
    }
    *reinterpret_cast<float4*>(o + (size_t)node * os + oc0 + q * 4) = acc;
}

// -------------------------------------------------------------------------
__device__ __forceinline__ void fma4(float4& c, float s, const float4& v)
{
    c.x += s * v.x; c.y += s * v.y; c.z += s * v.z; c.w += s * v.w;
}

// in-place GEMM: out[r,:] = out[r,:] @ W + indeg_raw[r]*b1.
// 32 rows/block, full 128 cols (rows staged to smem before overwrite).
__global__ __launch_bounds__(256)
void k_gemm(const float* __restrict__ W,
            const float* __restrict__ b1,
            float*       __restrict__ out, int n)
{
    __shared__ float As[32 * 128];   // [r][k], 16 KB
    int tid  = threadIdx.x;
    int row0 = blockIdx.x * 32;

    for (int i = tid; i < 32 * 32; i += 256) {
        int r  = i >> 5;
        int kc = i & 31;
        int gr = row0 + r;
        float4 v = (gr < n)
            ? reinterpret_cast<const float4*>(out + (size_t)gr * DD)[kc]
            : make_float4(0.f, 0.f, 0.f, 0.f);
        reinterpret_cast<float4*>(As)[i] = v;
    }
    __syncthreads();

    int r = tid >> 3;       // 0..31
    int q = tid & 7;        // float4-cols {q, q+8, q+16, q+24}

    float4 a0 = make_float4(0.f, 0.f, 0.f, 0.f);
    float4 a1 = a0, a2 = a0, a3 = a0;

    const float4* W4 = reinterpret_cast<const float4*>(W);
    const float*  Ar = As + r * 128;

    #pragma unroll 4
    for (int k = 0; k < 128; k++) {
        float a = Ar[k];
        fma4(a0, a, W4[k * 32 + q]);
        fma4(a1, a, W4[k * 32 + q + 8]);
        fma4(a2, a, W4[k * 32 + q + 16]);
        fma4(a3, a, W4[k * 32 + q + 24]);
    }

    int gr = row0 + r;
    if (gr < n) {
        float dg = (float)g_deg_d[gr];                 // raw in-degree
        const float4* b4 = reinterpret_cast<const float4*>(b1);
        float4* op = reinterpret_cast<float4*>(out + (size_t)gr * DD);
        float4 b, o;
        b = b4[q];      o.x=a0.x+dg*b.x; o.y=a0.y+dg*b.y; o.z=a0.z+dg*b.z; o.w=a0.w+dg*b.w; op[q]      = o;
        b = b4[q + 8];  o.x=a1.x+dg*b.x; o.y=a1.y+dg*b.y; o.z=a1.z+dg*b.z; o.w=a1.w+dg*b.w; op[q + 8]  = o;
        b = b4[q + 16]; o.x=a2.x+dg*b.x; o.y=a2.y+dg*b.y; o.z=a2.z+dg*b.z; o.w=a2.w+dg*b.w; op[q + 16] = o;
        b = b4[q + 24]; o.x=a3.x+dg*b.x; o.y=a3.y+dg*b.y; o.z=a3.z+dg*b.z; o.w=a3.w+dg*b.w; op[q + 24] = o;
    }
}

// -------------------------------------------------------------------------
extern "C" void kernel_launch(void* const* d_in, const int* in_sizes, int n_in,
                              void* d_out, int out_size)
{
    const float* feat = (const float*)d_in[0];
    const int*   src  = (const int*)  d_in[1];
    const int*   dst  = (const int*)  d_in[2];
    const float* W1   = (const float*)d_in[3];
    const float* b0   = (const float*)d_in[4];
    const float* b1   = (const float*)d_in[5];
    float*       out  = (float*)d_out;

    int E = in_sizes[1];
    if (E > MAXE) E = MAXE;
    int N = out_size / DD;
    if (N > MAXN) N = MAXN;

    float* s4 = nullptr;
    cudaGetSymbolAddress((void**)&s4, g_s4);   // host-side query; capture-safe

    dim3 blk(256);
    int gN  = (N + 255) / 256;
    int gE  = (E + 255) / 256;
    int nb  = (N + 1023) / 1024;
    int gC4 = (N * 4 + 255) / 256;   // 16-col csr launches
    int gC1 = gN;                    // 4-col csr launches

    // ---- build degrees + CSR (by dst) ----
    k_init<<<gN, blk>>>(N);
    k_deg<<<gE, blk>>>(src, dst, E);
    k_scan1<<<nb, 1024>>>(N);
    k_scan2<<<1, 32>>>(nb);
    k_scan3<<<gN, blk>>>(N, E);
    k_fill<<<gE, blk>>>(src, dst, E);

    // ---- slices 0..6 (16 cols each), scratch = next slice's region ----
    for (int s = 0; s < 7; s++) {
        int c0  = s * 16;
        int sc0 = c0 + 16;
        k_csr<4, 0><<<gC4, blk>>>(feat, DD, c0, out, DD, c0,  b0, N);
        k_csr<4, 1><<<gC4, blk>>>(out,  DD, c0, out, DD, sc0, b0, N);
        k_csr<4, 2><<<gC4, blk>>>(out,  DD, sc0, out, DD, c0, b0, N);
    }

    // ---- slice 7 (cols 112..127) in four 4-col chunks via g_s4 ----
    for (int t = 0; t < 4; t++) {
        int c = 112 + t * 4;
        k_csr<1, 0><<<gC1, blk>>>(feat, DD, c, out, DD, c, b0, N);
        k_csr<1, 1><<<gC1, blk>>>(out,  DD, c, s4,  4,  0, b0, N);
        k_csr<1, 2><<<gC1, blk>>>(s4,   4,  0, out, DD, c, b0, N);
    }

    // ---- in-place: out = out @ W1 + indeg_raw * b1 ----
    int gG = (N + 31) / 32;
    k_gemm<<<gG, blk>>>(W1, b1, out, N);
}

// round 11
// speedup vs baseline: 2.0918x; 1.6530x over previous
#include <cuda_runtime.h>

#define MAXN 100000
#define MAXE 650000
#define DD   128

// ---- device globals (~11 MB total) ----
__device__ int   g_deg_s[MAXN];            // out-degree
__device__ int   g_deg_d[MAXN];            // in-degree (row lengths + bias)
__device__ int   g_rowptr[MAXN + 1];
__device__ int   g_cursor[MAXN];
__device__ int   g_csrc[MAXE];             // src of each edge, grouped by dst
__device__ int   g_bsum[128];
__device__ float g_s16[(size_t)MAXN * 16]; // 6.4 MB 16-col slice scratch

// -------------------------------------------------------------------------
__global__ void k_init(int n)
{
    int i = blockIdx.x * blockDim.x + threadIdx.x;
    if (i < n) { g_deg_s[i] = 0; g_deg_d[i] = 0; }
}

__global__ void k_deg(const int* __restrict__ src, const int* __restrict__ dst, int E)
{
    int i = blockIdx.x * blockDim.x + threadIdx.x;
    if (i < E) {
        atomicAdd(&g_deg_s[src[i]], 1);
        atomicAdd(&g_deg_d[dst[i]], 1);
    }
}

// exclusive scan of g_deg_d -> g_rowptr (block-local) + block sums
__global__ void k_scan1(int n)
{
    __shared__ int s[1024];
    int t = threadIdx.x;
    int i = blockIdx.x * 1024 + t;
    int v = (i < n) ? g_deg_d[i] : 0;
    s[t] = v;
    __syncthreads();
    for (int off = 1; off < 1024; off <<= 1) {
        int x = (t >= off) ? s[t - off] : 0;
        __syncthreads();
        s[t] += x;
        __syncthreads();
    }
    if (i < n) g_rowptr[i] = s[t] - v;
    if (t == 1023) g_bsum[blockIdx.x] = s[1023];
}

// parallel exclusive scan of block sums (nb <= 128)
__global__ void k_scan2(int nb)
{
    __shared__ int s[128];
    int t = threadIdx.x;
    int v = (t < nb) ? g_bsum[t] : 0;
    s[t] = v;
    __syncthreads();
    for (int off = 1; off < 128; off <<= 1) {
        int x = (t >= off) ? s[t - off] : 0;
        __syncthreads();
        s[t] += x;
        __syncthreads();
    }
    if (t < nb) g_bsum[t] = s[t] - v;
}

__global__ void k_scan3(int n, int E)
{
    int i = blockIdx.x * blockDim.x + threadIdx.x;
    if (i < n) {
        int r = g_rowptr[i] + g_bsum[i >> 10];
        g_rowptr[i] = r;
        g_cursor[i] = r;
    }
    if (i == 0) g_rowptr[n] = E;
}

__global__ void k_fill(const int* __restrict__ src, const int* __restrict__ dst, int E)
{
    int e = blockIdx.x * blockDim.x + threadIdx.x;
    if (e < E) {
        int pos = atomicAdd(&g_cursor[dst[e]], 1);
        g_csrc[pos] = src[e];
    }
}

// -------------------------------------------------------------------------
// Pass A (layer 0, FULL width): warp per node, lane = one float4 of the row.
// out[node,:] = (sum_{s in N(node)} feat[s,:]*io[s]) * ii[node] + b0) * io[node]
__global__ void k_pullA(const float* __restrict__ feat,
                        const float* __restrict__ b0,
                        float* __restrict__ out, int n)
{
    int w    = (blockIdx.x * blockDim.x + threadIdx.x) >> 5;
    int lane = threadIdx.x & 31;
    if (w >= n) return;

    int beg = g_rowptr[w];
    int end = g_rowptr[w + 1];

    float4 acc = make_float4(0.f, 0.f, 0.f, 0.f);
    int j = beg;
    for (; j + 4 <= end; j += 4) {
        int s0 = g_csrc[j],     s1 = g_csrc[j + 1];
        int s2 = g_csrc[j + 2], s3 = g_csrc[j + 3];
        float i0 = rsqrtf((float)max(g_deg_s[s0], 1));
        float i1 = rsqrtf((float)max(g_deg_s[s1], 1));
        float i2 = rsqrtf((float)max(g_deg_s[s2], 1));
        float i3 = rsqrtf((float)max(g_deg_s[s3], 1));
        float4 v0 = *reinterpret_cast<const float4*>(feat + (size_t)s0 * DD + lane * 4);
        float4 v1 = *reinterpret_cast<const float4*>(feat + (size_t)s1 * DD + lane * 4);
        float4 v2 = *reinterpret_cast<const float4*>(feat + (size_t)s2 * DD + lane * 4);
        float4 v3 = *reinterpret_cast<const float4*>(feat + (size_t)s3 * DD + lane * 4);
        acc.x += v0.x * i0 + v1.x * i1 + v2.x * i2 + v3.x * i3;
        acc.y += v0.y * i0 + v1.y * i1 + v2.y * i2 + v3.y * i3;
        acc.z += v0.z * i0 + v1.z * i1 + v2.z * i2 + v3.z * i3;
        acc.w += v0.w * i0 + v1.w * i1 + v2.w * i2 + v3.w * i3;
    }
    for (; j < end; j++) {
        int s = g_csrc[j];
        float sc = rsqrtf((float)max(g_deg_s[s], 1));
        float4 v = *reinterpret_cast<const float4*>(feat + (size_t)s * DD + lane * 4);
        acc.x += v.x * sc; acc.y += v.y * sc; acc.z += v.z * sc; acc.w += v.w * sc;
    }

    float ii = rsqrtf((float)max(g_deg_d[w], 1));
    float io = rsqrtf((float)max(g_deg_s[w], 1));
    float4 b = reinterpret_cast<const float4*>(b0)[lane];
    acc.x = (acc.x * ii + b.x) * io;
    acc.y = (acc.y * ii + b.y) * io;
    acc.z = (acc.z * ii + b.z) * io;
    acc.w = (acc.w * ii + b.w) * io;
    *reinterpret_cast<float4*>(out + (size_t)w * DD + lane * 4) = acc;
}

// Passes B/C (16-col slices): thread per (node, q), q in 0..3.
// MODE 1 (B): o = ii * sum x[src]    MODE 2 (C): o = sum x[src]
template <int MODE>
__global__ void k_pullBC(const float* __restrict__ x, int xs, int xc0,
                         float* __restrict__ o, int os, int oc0, int n)
{
    int t = blockIdx.x * blockDim.x + threadIdx.x;
    int node = t >> 2;
    int q    = t & 3;
    if (node >= n) return;

    int beg = g_rowptr[node];
    int end = g_rowptr[node + 1];

    float4 acc = make_float4(0.f, 0.f, 0.f, 0.f);
    int j = beg;
    for (; j + 4 <= end; j += 4) {
        int s0 = g_csrc[j],     s1 = g_csrc[j + 1];
        int s2 = g_csrc[j + 2], s3 = g_csrc[j + 3];
        float4 v0 = *reinterpret_cast<const float4*>(x + (size_t)s0 * xs + xc0 + q * 4);
        float4 v1 = *reinterpret_cast<const float4*>(x + (size_t)s1 * xs + xc0 + q * 4);
        float4 v2 = *reinterpret_cast<const float4*>(x + (size_t)s2 * xs + xc0 + q * 4);
        float4 v3 = *reinterpret_cast<const float4*>(x + (size_t)s3 * xs + xc0 + q * 4);
        acc.x += v0.x + v1.x + v2.x + v3.x;
        acc.y += v0.y + v1.y + v2.y + v3.y;
        acc.z += v0.z + v1.z + v2.z + v3.z;
        acc.w += v0.w + v1.w + v2.w + v3.w;
    }
    for (; j < end; j++) {
        int s = g_csrc[j];
        float4 v = *reinterpret_cast<const float4*>(x + (size_t)s * xs + xc0 + q * 4);
        acc.x += v.x; acc.y += v.y; acc.z += v.z; acc.w += v.w;
    }

    if (MODE == 1) {
        float ii = rsqrtf((float)max(g_deg_d[node], 1));
        acc.x *= ii; acc.y *= ii; acc.z *= ii; acc.w *= ii;
    }
    *reinterpret_cast<float4*>(o + (size_t)node * os + oc0 + q * 4) = acc;
}

// -------------------------------------------------------------------------
__device__ __forceinline__ void fma4(float4& c, float s, const float4& v)
{
    c.x += s * v.x; c.y += s * v.y; c.z += s * v.z; c.w += s * v.w;
}

// in-place GEMM: out[r,:] = out[r,:] @ W + indeg_raw[r]*b1.
// 96 rows/block (48 KB smem, [k][r] layout = conflict-free), 3 rows x 16
// cols per thread (W loads amortized over 3 rows).
__global__ __launch_bounds__(256)
void k_gemm(const float* __restrict__ W,
            const float* __restrict__ b1,
            float*       __restrict__ out, int n)
{
    __shared__ float As[128 * 96];   // [k][r], 48 KB
    int tid  = threadIdx.x;
    int row0 = blockIdx.x * 96;

    // stage 96 rows, transposed to [k][r]
    for (int i = tid; i < 96 * 32; i += 256) {
        int r  = i % 96;
        int kc = i / 96;           // float4 k-chunk 0..31
        int gr = row0 + r;
        float4 v = (gr < n)
            ? reinterpret_cast<const float4*>(out + (size_t)gr * DD)[kc]
            : make_float4(0.f, 0.f, 0.f, 0.f);
        As[(kc * 4 + 0) * 96 + r] = v.x;
        As[(kc * 4 + 1) * 96 + r] = v.y;
        As[(kc * 4 + 2) * 96 + r] = v.z;
        As[(kc * 4 + 3) * 96 + r] = v.w;
    }
    __syncthreads();

    int r = tid >> 3;       // 0..31: rows r, r+32, r+64
    int q = tid & 7;        // float4-cols {q, q+8, q+16, q+24}

    float4 z = make_float4(0.f, 0.f, 0.f, 0.f);
    float4 c00 = z, c01 = z, c02 = z, c03 = z;
    float4 c10 = z, c11 = z, c12 = z, c13 = z;
    float4 c20 = z, c21 = z, c22 = z, c23 = z;

    const float4* W4 = reinterpret_cast<const float4*>(W);

    #pragma unroll 4
    for (int k = 0; k < 128; k++) {
        float a0 = As[k * 96 + r];
        float a1 = As[k * 96 + r + 32];
        float a2 = As[k * 96 + r + 64];
        float4 w0 = W4[k * 32 + q];
        float4 w1 = W4[k * 32 + q + 8];
        float4 w2 = W4[k * 32 + q + 16];
        float4 w3 = W4[k * 32 + q + 24];
        fma4(c00, a0, w0); fma4(c01, a0, w1); fma4(c02, a0, w2); fma4(c03, a0, w3);
        fma4(c10, a1, w0); fma4(c11, a1, w1); fma4(c12, a1, w2); fma4(c13, a1, w3);
        fma4(c20, a2, w0); fma4(c21, a2, w1); fma4(c22, a2, w2); fma4(c23, a2, w3);
    }

    const float4* b4 = reinterpret_cast<const float4*>(b1);
    float4 bb0 = b4[q], bb1 = b4[q + 8], bb2 = b4[q + 16], bb3 = b4[q + 24];

    for (int i = 0; i < 3; i++) {
        int gr = row0 + r + i * 32;
        if (gr >= n) continue;
        float dg = (float)g_deg_d[gr];                 // raw in-degree
        float4 s0 = (i == 0) ? c00 : (i == 1) ? c10 : c20;
        float4 s1 = (i == 0) ? c01 : (i == 1) ? c11 : c21;
        float4 s2 = (i == 0) ? c02 : (i == 1) ? c12 : c22;
        float4 s3 = (i == 0) ? c03 : (i == 1) ? c13 : c23;
        float4* op = reinterpret_cast<float4*>(out + (size_t)gr * DD);
        float4 o;
        o.x=s0.x+dg*bb0.x; o.y=s0.y+dg*bb0.y; o.z=s0.z+dg*bb0.z; o.w=s0.w+dg*bb0.w; op[q]      = o;
        o.x=s1.x+dg*bb1.x; o.y=s1.y+dg*bb1.y; o.z=s1.z+dg*bb1.z; o.w=s1.w+dg*bb1.w; op[q + 8]  = o;
        o.x=s2.x+dg*bb2.x; o.y=s2.y+dg*bb2.y; o.z=s2.z+dg*bb2.z; o.w=s2.w+dg*bb2.w; op[q + 16] = o;
        o.x=s3.x+dg*bb3.x; o.y=s3.y+dg*bb3.y; o.z=s3.z+dg*bb3.z; o.w=s3.w+dg*bb3.w; op[q + 24] = o;
    }
}

// -------------------------------------------------------------------------
extern "C" void kernel_launch(void* const* d_in, const int* in_sizes, int n_in,
                              void* d_out, int out_size)
{
    const float* feat = (const float*)d_in[0];
    const int*   src  = (const int*)  d_in[1];
    const int*   dst  = (const int*)  d_in[2];
    const float* W1   = (const float*)d_in[3];
    const float* b0   = (const float*)d_in[4];
    const float* b1   = (const float*)d_in[5];
    float*       out  = (float*)d_out;

    int E = in_sizes[1];
    if (E > MAXE) E = MAXE;
    int N = out_size / DD;
    if (N > MAXN) N = MAXN;

    float* s16 = nullptr;
    cudaGetSymbolAddress((void**)&s16, g_s16);   // host-side query; capture-safe

    dim3 blk(256);
    int gN  = (N + 255) / 256;
    int gE  = (E + 255) / 256;
    int nb  = (N + 1023) / 1024;
    int gA  = (N * 32 + 255) / 256;   // warp per node
    int gBC = (N * 4 + 255) / 256;    // thread per (node, q)

    // ---- build degrees + CSR (grouped by dst) ----
    k_init<<<gN, blk>>>(N);
    k_deg<<<gE, blk>>>(src, dst, E);
    k_scan1<<<nb, 1024>>>(N);
    k_scan2<<<1, 128>>>(nb);
    k_scan3<<<gN, blk>>>(N, E);
    k_fill<<<gE, blk>>>(src, dst, E);

    // ---- pass A: layer 0, full width, into d_out ----
    k_pullA<<<gA, blk>>>(feat, b0, out, N);

    // ---- passes B/C per 16-col slice through the 6.4 MB scratch ----
    for (int s = 0; s < 8; s++) {
        int c0 = s * 16;
        k_pullBC<1><<<gBC, blk>>>(out, DD, c0, s16, 16, 0, N);  // g1 slice
        k_pullBC<2><<<gBC, blk>>>(s16, 16, 0, out, DD, c0, N);  // final sum
    }

    // ---- in-place: out = out @ W1 + indeg_raw * b1 ----
    int gG = (N + 95) / 96;
    k_gemm<<<gG, blk>>>(W1, b1, out, N);
}

// round 14
// speedup vs baseline: 2.5402x; 1.2144x over previous
#include <cuda_runtime.h>
#include <cstdint>

#define MAXN 100000
#define MAXE 650000
#define DD   128
#define WTS  132                         // padded WT stride (conflict-free)
#define GEMM_SMEM (128 * WTS * 4)        // 67584 B dynamic smem

// ---- device globals (~11 MB total) ----
__device__ int   g_deg_s[MAXN];            // out-degree
__device__ int   g_deg_d[MAXN];            // in-degree (row lengths + bias)
__device__ int   g_rowptr[MAXN + 1];
__device__ int   g_cursor[MAXN];
__device__ int   g_csrc[MAXE];             // src of each edge, grouped by dst
__device__ int   g_bsum[128];
__device__ float g_s16[(size_t)MAXN * 16]; // 6.4 MB 16-col slice scratch

// -------------------------------------------------------------------------
__global__ void k_init(int n)
{
    int i = blockIdx.x * blockDim.x + threadIdx.x;
    if (i < n) { g_deg_s[i] = 0; g_deg_d[i] = 0; }
}

__global__ void k_deg(const int* __restrict__ src, const int* __restrict__ dst, int E)
{
    int i = blockIdx.x * blockDim.x + threadIdx.x;
    if (i < E) {
        atomicAdd(&g_deg_s[src[i]], 1);
        atomicAdd(&g_deg_d[dst[i]], 1);
    }
}

__global__ void k_scan1(int n)
{
    __shared__ int s[1024];
    int t = threadIdx.x;
    int i = blockIdx.x * 1024 + t;
    int v = (i < n) ? g_deg_d[i] : 0;
    s[t] = v;
    __syncthreads();
    for (int off = 1; off < 1024; off <<= 1) {
        int x = (t >= off) ? s[t - off] : 0;
        __syncthreads();
        s[t] += x;
        __syncthreads();
    }
    if (i < n) g_rowptr[i] = s[t] - v;
    if (t == 1023) g_bsum[blockIdx.x] = s[1023];
}

__global__ void k_scan2(int nb)
{
    __shared__ int s[128];
    int t = threadIdx.x;
    int v = (t < nb) ? g_bsum[t] : 0;
    s[t] = v;
    __syncthreads();
    for (int off = 1; off < 128; off <<= 1) {
        int x = (t >= off) ? s[t - off] : 0;
        __syncthreads();
        s[t] += x;
        __syncthreads();
    }
    if (t < nb) g_bsum[t] = s[t] - v;
}

__global__ void k_scan3(int n, int E)
{
    int i = blockIdx.x * blockDim.x + threadIdx.x;
    if (i < n) {
        int r = g_rowptr[i] + g_bsum[i >> 10];
        g_rowptr[i] = r;
        g_cursor[i] = r;
    }
    if (i == 0) g_rowptr[n] = E;
}

__global__ void k_fill(const int* __restrict__ src, const int* __restrict__ dst, int E)
{
    int e = blockIdx.x * blockDim.x + threadIdx.x;
    if (e < E) {
        int pos = atomicAdd(&g_cursor[dst[e]], 1);
        g_csrc[pos] = src[e];
    }
}

// -------------------------------------------------------------------------
// Pass A (layer 0, full width): warp per node, lane = one float4 of the row.
__global__ void k_pullA(const float* __restrict__ feat,
                        const float* __restrict__ b0,
                        float* __restrict__ out, int n)
{
    int w    = (blockIdx.x * blockDim.x + threadIdx.x) >> 5;
    int lane = threadIdx.x & 31;
    if (w >= n) return;

    int beg = g_rowptr[w];
    int end = g_rowptr[w + 1];

    float4 acc = make_float4(0.f, 0.f, 0.f, 0.f);
    int j = beg;
    for (; j + 4 <= end; j += 4) {
        int s0 = g_csrc[j],     s1 = g_csrc[j + 1];
        int s2 = g_csrc[j + 2], s3 = g_csrc[j + 3];
        float i0 = rsqrtf((float)max(g_deg_s[s0], 1));
        float i1 = rsqrtf((float)max(g_deg_s[s1], 1));
        float i2 = rsqrtf((float)max(g_deg_s[s2], 1));
        float i3 = rsqrtf((float)max(g_deg_s[s3], 1));
        float4 v0 = *reinterpret_cast<const float4*>(feat + (size_t)s0 * DD + lane * 4);
        float4 v1 = *reinterpret_cast<const float4*>(feat + (size_t)s1 * DD + lane * 4);
        float4 v2 = *reinterpret_cast<const float4*>(feat + (size_t)s2 * DD + lane * 4);
        float4 v3 = *reinterpret_cast<const float4*>(feat + (size_t)s3 * DD + lane * 4);
        acc.x += v0.x * i0 + v1.x * i1 + v2.x * i2 + v3.x * i3;
        acc.y += v0.y * i0 + v1.y * i1 + v2.y * i2 + v3.y * i3;
        acc.z += v0.z * i0 + v1.z * i1 + v2.z * i2 + v3.z * i3;
        acc.w += v0.w * i0 + v1.w * i1 + v2.w * i2 + v3.w * i3;
    }
    for (; j < end; j++) {
        int s = g_csrc[j];
        float sc = rsqrtf((float)max(g_deg_s[s], 1));
        float4 v = *reinterpret_cast<const float4*>(feat + (size_t)s * DD + lane * 4);
        acc.x += v.x * sc; acc.y += v.y * sc; acc.z += v.z * sc; acc.w += v.w * sc;
    }

    float ii = rsqrtf((float)max(g_deg_d[w], 1));
    float io = rsqrtf((float)max(g_deg_s[w], 1));
    float4 b = reinterpret_cast<const float4*>(b0)[lane];
    acc.x = (acc.x * ii + b.x) * io;
    acc.y = (acc.y * ii + b.y) * io;
    acc.z = (acc.z * ii + b.z) * io;
    acc.w = (acc.w * ii + b.w) * io;
    *reinterpret_cast<float4*>(out + (size_t)w * DD + lane * 4) = acc;
}

// Passes B/C (16-col slices): thread per (node, q); unroll-8 gathers (MLP 8).
// MODE 1 (B): o = ii * sum x[src]    MODE 2 (C): o = sum x[src]
template <int MODE>
__global__ void k_pullBC(const float* __restrict__ x, int xs, int xc0,
                         float* __restrict__ o, int os, int oc0, int n)
{
    int t = blockIdx.x * blockDim.x + threadIdx.x;
    int node = t >> 2;
    int q    = t & 3;
    if (node >= n) return;

    int beg = g_rowptr[node];
    int end = g_rowptr[node + 1];

    float4 acc = make_float4(0.f, 0.f, 0.f, 0.f);
    int j = beg;
    for (; j + 8 <= end; j += 8) {
        int s0 = g_csrc[j],     s1 = g_csrc[j + 1];
        int s2 = g_csrc[j + 2], s3 = g_csrc[j + 3];
        int s4 = g_csrc[j + 4], s5 = g_csrc[j + 5];
        int s6 = g_csrc[j + 6], s7 = g_csrc[j + 7];
        float4 v0 = *reinterpret_cast<const float4*>(x + (size_t)s0 * xs + xc0 + q * 4);
        float4 v1 = *reinterpret_cast<const float4*>(x + (size_t)s1 * xs + xc0 + q * 4);
        float4 v2 = *reinterpret_cast<const float4*>(x + (size_t)s2 * xs + xc0 + q * 4);
        float4 v3 = *reinterpret_cast<const float4*>(x + (size_t)s3 * xs + xc0 + q * 4);
        float4 v4 = *reinterpret_cast<const float4*>(x + (size_t)s4 * xs + xc0 + q * 4);
        float4 v5 = *reinterpret_cast<const float4*>(x + (size_t)s5 * xs + xc0 + q * 4);
        float4 v6 = *reinterpret_cast<const float4*>(x + (size_t)s6 * xs + xc0 + q * 4);
        float4 v7 = *reinterpret_cast<const float4*>(x + (size_t)s7 * xs + xc0 + q * 4);
        acc.x += ((v0.x + v1.x) + (v2.x + v3.x)) + ((v4.x + v5.x) + (v6.x + v7.x));
        acc.y += ((v0.y + v1.y) + (v2.y + v3.y)) + ((v4.y + v5.y) + (v6.y + v7.y));
        acc.z += ((v0.z + v1.z) + (v2.z + v3.z)) + ((v4.z + v5.z) + (v6.z + v7.z));
        acc.w += ((v0.w + v1.w) + (v2.w + v3.w)) + ((v4.w + v5.w) + (v6.w + v7.w));
    }
    for (; j < end; j++) {
        int s = g_csrc[j];
        float4 v = *reinterpret_cast<const float4*>(x + (size_t)s * xs + xc0 + q * 4);
        acc.x += v.x; acc.y += v.y; acc.z += v.z; acc.w += v.w;
    }

    if (MODE == 1) {
        float ii = rsqrtf((float)max(g_deg_d[node], 1));
        acc.x *= ii; acc.y *= ii; acc.z *= ii; acc.w *= ii;
    }
    *reinterpret_cast<float4*>(o + (size_t)node * os + oc0 + q * 4) = acc;
}

// -------------------------------------------------------------------------
// tf32 helpers
__device__ __forceinline__ float tf32f(float f)
{
    unsigned int r;
    asm("cvt.rna.tf32.f32 %0, %1;" : "=r"(r) : "f"(f));
    return __uint_as_float(r);
}

__device__ __forceinline__ void mma_tf32(float4& d,
                                         unsigned int a0, unsigned int a1,
                                         unsigned int a2, unsigned int a3,
                                         unsigned int b0, unsigned int b1)
{
    asm volatile(
        "mma.sync.aligned.m16n8k8.row.col.f32.tf32.tf32.f32 "
        "{%0,%1,%2,%3}, {%4,%5,%6,%7}, {%8,%9}, {%0,%1,%2,%3};"
        : "+f"(d.x), "+f"(d.y), "+f"(d.z), "+f"(d.w)
        : "r"(a0), "r"(a1), "r"(a2), "r"(a3), "r"(b0), "r"(b1));
}

// tensor-core GEMM, in place: out[r,:] = out[r,:] @ W + indeg_raw[r]*b1.
// 128 rows/block, 8 warps (16 rows each, all 128 cols). W transposed +
// tf32-converted into padded smem once per block; A fragments read directly
// from global (each element used once; rows read == rows written by the
// same warp, so in-place is safe).
__global__ __launch_bounds__(256)
void k_gemm(const float* __restrict__ W,
            const float* __restrict__ b1,
            float*       __restrict__ out, int n)
{
    extern __shared__ float WT[];    // [col][k], stride WTS=132
    int tid = threadIdx.x;

    for (int i = tid; i < 128 * 32; i += 256) {
        int k  = i >> 5;
        int c4 = i & 31;
        float4 v = __ldg(reinterpret_cast<const float4*>(W) + k * 32 + c4);
        int c = c4 * 4;
        WT[(c + 0) * WTS + k] = tf32f(v.x);
        WT[(c + 1) * WTS + k] = tf32f(v.y);
        WT[(c + 2) * WTS + k] = tf32f(v.z);
        WT[(c + 3) * WTS + k] = tf32f(v.w);
    }
    __syncthreads();

    int warp = tid >> 5;
    int lane = tid & 31;
    int g    = lane >> 2;        // groupID 0..7
    int tg   = lane & 3;         // thread-in-group 0..3

    int rbase = blockIdx.x * 128 + warp * 16;
    int r_lo  = rbase + g;
    int r_hi  = rbase + g + 8;
    int rl = min(r_lo, n - 1);
    int rh = min(r_hi, n - 1);
    const float* Alo = out + (size_t)rl * DD;
    const float* Ahi = out + (size_t)rh * DD;

    float4 acc[16];
    #pragma unroll
    for (int nt = 0; nt < 16; nt++) acc[nt] = make_float4(0.f, 0.f, 0.f, 0.f);

    #pragma unroll 2
    for (int kt = 0; kt < 16; kt++) {
        int k0 = kt * 8;
        unsigned int a0 = __float_as_uint(tf32f(Alo[k0 + tg]));
        unsigned int a1 = __float_as_uint(tf32f(Ahi[k0 + tg]));
        unsigned int a2 = __float_as_uint(tf32f(Alo[k0 + tg + 4]));
        unsigned int a3 = __float_as_uint(tf32f(Ahi[k0 + tg + 4]));
        #pragma unroll
        for (int nt = 0; nt < 16; nt++) {
            const float* wp = WT + (nt * 8 + g) * WTS + k0 + tg;
            unsigned int b0 = __float_as_uint(wp[0]);
            unsigned int bv = __float_as_uint(wp[4]);
            mma_tf32(acc[nt], a0, a1, a2, a3, b0, bv);
        }
    }

    float dgl = (float)g_deg_d[rl];
    float dgh = (float)g_deg_d[rh];
    #pragma unroll
    for (int nt = 0; nt < 16; nt++) {
        int c = nt * 8 + tg * 2;
        float2 b = *reinterpret_cast<const float2*>(b1 + c);
        if (r_lo < n) {
            float2 o; o.x = acc[nt].x + dgl * b.x; o.y = acc[nt].y + dgl * b.y;
            *reinterpret_cast<float2*>(out + (size_t)r_lo * DD + c) = o;
        }
        if (r_hi < n) {
            float2 o; o.x = acc[nt].z + dgh * b.x; o.y = acc[nt].w + dgh * b.y;
            *reinterpret_cast<float2*>(out + (size_t)r_hi * DD + c) = o;
        }
    }
}

// -------------------------------------------------------------------------
extern "C" void kernel_launch(void* const* d_in, const int* in_sizes, int n_in,
                              void* d_out, int out_size)
{
    const float* feat = (const float*)d_in[0];
    const int*   src  = (const int*)  d_in[1];
    const int*   dst  = (const int*)  d_in[2];
    const float* W1   = (const float*)d_in[3];
    const float* b0   = (const float*)d_in[4];
    const float* b1   = (const float*)d_in[5];
    float*       out  = (float*)d_out;

    int E = in_sizes[1];
    if (E > MAXE) E = MAXE;
    int N = out_size / DD;
    if (N > MAXN) N = MAXN;

    float* s16 = nullptr;
    cudaGetSymbolAddress((void**)&s16, g_s16);   // host-side query; capture-safe

    cudaFuncSetAttribute(k_gemm, cudaFuncAttributeMaxDynamicSharedMemorySize,
                         GEMM_SMEM);             // attribute set; capture-safe

    dim3 blk(256);
    int gN  = (N + 255) / 256;
    int gE  = (E + 255) / 256;
    int nb  = (N + 1023) / 1024;
    int gA  = (N * 32 + 255) / 256;   // warp per node
    int gBC = (N * 4 + 255) / 256;    // thread per (node, q)

    // ---- build degrees + CSR (grouped by dst) ----
    k_init<<<gN, blk>>>(N);
    k_deg<<<gE, blk>>>(src, dst, E);
    k_scan1<<<nb, 1024>>>(N);
    k_scan2<<<1, 128>>>(nb);
    k_scan3<<<gN, blk>>>(N, E);
    k_fill<<<gE, blk>>>(src, dst, E);

    // ---- pass A: layer 0, full width, into d_out ----
    k_pullA<<<gA, blk>>>(feat, b0, out, N);

    // ---- passes B/C per 16-col slice through the 6.4 MB scratch ----
    for (int s = 0; s < 8; s++) {
        int c0 = s * 16;
        k_pullBC<1><<<gBC, blk>>>(out, DD, c0, s16, 16, 0, N);  // g1 slice
        k_pullBC<2><<<gBC, blk>>>(s16, 16, 0, out, DD, c0, N);  // final sum
    }

    // ---- in-place tensor-core GEMM: out = out @ W1 + indeg_raw * b1 ----
    int gG = (N + 127) / 128;
    k_gemm<<<gG, blk, GEMM_SMEM>>>(W1, b1, out, N);
}

// round 15
// speedup vs baseline: 3.1893x; 1.2555x over previous
#include <cuda_runtime.h>
#include <cstdint>

#define MAXN 100000
#define MAXE 650000
#define DD   128
#define WTS  132                         // padded WT stride (conflict-free)
#define GEMM_SMEM (128 * WTS * 4)        // 67584 B dynamic smem

// ---- device globals (~17.4 MB total) ----
__device__ int   g_deg_s[MAXN];            // out-degree
__device__ int   g_deg_d[MAXN];            // in-degree (row lengths + bias)
__device__ int   g_rowptr[MAXN + 1];
__device__ int   g_cursor[MAXN];
__device__ int   g_csrc[MAXE];             // src of each edge, grouped by dst
__device__ int   g_bsum[128];
__device__ float g_s32[(size_t)MAXN * 32]; // 12.8 MB 32-col slice scratch

// -------------------------------------------------------------------------
__global__ void k_init(int n)
{
    int i = blockIdx.x * blockDim.x + threadIdx.x;
    if (i < n) { g_deg_s[i] = 0; g_deg_d[i] = 0; }
}

__global__ void k_deg(const int* __restrict__ src, const int* __restrict__ dst, int E)
{
    int i = blockIdx.x * blockDim.x + threadIdx.x;
    if (i < E) {
        atomicAdd(&g_deg_s[src[i]], 1);
        atomicAdd(&g_deg_d[dst[i]], 1);
    }
}

__global__ void k_scan1(int n)
{
    __shared__ int s[1024];
    int t = threadIdx.x;
    int i = blockIdx.x * 1024 + t;
    int v = (i < n) ? g_deg_d[i] : 0;
    s[t] = v;
    __syncthreads();
    for (int off = 1; off < 1024; off <<= 1) {
        int x = (t >= off) ? s[t - off] : 0;
        __syncthreads();
        s[t] += x;
        __syncthreads();
    }
    if (i < n) g_rowptr[i] = s[t] - v;
    if (t == 1023) g_bsum[blockIdx.x] = s[1023];
}

__global__ void k_scan2(int nb)
{
    __shared__ int s[128];
    int t = threadIdx.x;
    int v = (t < nb) ? g_bsum[t] : 0;
    s[t] = v;
    __syncthreads();
    for (int off = 1; off < 128; off <<= 1) {
        int x = (t >= off) ? s[t - off] : 0;
        __syncthreads();
        s[t] += x;
        __syncthreads();
    }
    if (t < nb) g_bsum[t] = s[t] - v;
}

__global__ void k_scan3(int n, int E)
{
    int i = blockIdx.x * blockDim.x + threadIdx.x;
    if (i < n) {
        int r = g_rowptr[i] + g_bsum[i >> 10];
        g_rowptr[i] = r;
        g_cursor[i] = r;
    }
    if (i == 0) g_rowptr[n] = E;
}

__global__ void k_fill(const int* __restrict__ src, const int* __restrict__ dst, int E)
{
    int e = blockIdx.x * blockDim.x + threadIdx.x;
    if (e < E) {
        int pos = atomicAdd(&g_cursor[dst[e]], 1);
        g_csrc[pos] = src[e];
    }
}

// -------------------------------------------------------------------------
// Pass A (layer 0, full width): warp per node, lane = one float4 of the row.
__global__ void k_pullA(const float* __restrict__ feat,
                        const float* __restrict__ b0,
                        float* __restrict__ out, int n)
{
    int w    = (blockIdx.x * blockDim.x + threadIdx.x) >> 5;
    int lane = threadIdx.x & 31;
    if (w >= n) return;

    int beg = g_rowptr[w];
    int end = g_rowptr[w + 1];

    float4 acc = make_float4(0.f, 0.f, 0.f, 0.f);
    int j = beg;
    for (; j + 4 <= end; j += 4) {
        int s0 = g_csrc[j],     s1 = g_csrc[j + 1];
        int s2 = g_csrc[j + 2], s3 = g_csrc[j + 3];
        float i0 = rsqrtf((float)max(g_deg_s[s0], 1));
        float i1 = rsqrtf((float)max(g_deg_s[s1], 1));
        float i2 = rsqrtf((float)max(g_deg_s[s2], 1));
        float i3 = rsqrtf((float)max(g_deg_s[s3], 1));
        float4 v0 = *reinterpret_cast<const float4*>(feat + (size_t)s0 * DD + lane * 4);
        float4 v1 = *reinterpret_cast<const float4*>(feat + (size_t)s1 * DD + lane * 4);
        float4 v2 = *reinterpret_cast<const float4*>(feat + (size_t)s2 * DD + lane * 4);
        float4 v3 = *reinterpret_cast<const float4*>(feat + (size_t)s3 * DD + lane * 4);
        acc.x += v0.x * i0 + v1.x * i1 + v2.x * i2 + v3.x * i3;
        acc.y += v0.y * i0 + v1.y * i1 + v2.y * i2 + v3.y * i3;
        acc.z += v0.z * i0 + v1.z * i1 + v2.z * i2 + v3.z * i3;
        acc.w += v0.w * i0 + v1.w * i1 + v2.w * i2 + v3.w * i3;
    }
    for (; j < end; j++) {
        int s = g_csrc[j];
        float sc = rsqrtf((float)max(g_deg_s[s], 1));
        float4 v = *reinterpret_cast<const float4*>(feat + (size_t)s * DD + lane * 4);
        acc.x += v.x * sc; acc.y += v.y * sc; acc.z += v.z * sc; acc.w += v.w * sc;
    }

    float ii = rsqrtf((float)max(g_deg_d[w], 1));
    float io = rsqrtf((float)max(g_deg_s[w], 1));
    float4 b = reinterpret_cast<const float4*>(b0)[lane];
    acc.x = (acc.x * ii + b.x) * io;
    acc.y = (acc.y * ii + b.y) * io;
    acc.z = (acc.z * ii + b.z) * io;
    acc.w = (acc.w * ii + b.w) * io;
    *reinterpret_cast<float4*>(out + (size_t)w * DD + lane * 4) = acc;
}

// Passes B/C (32-col slices): 8 threads per node, one float4 per thread.
// MODE 1 (B): o = ii * sum x[src]    MODE 2 (C): o = sum x[src]
template <int MODE>
__global__ void k_pullBC(const float* __restrict__ x, int xs, int xc0,
                         float* __restrict__ o, int os, int oc0, int n)
{
    int t = blockIdx.x * blockDim.x + threadIdx.x;
    int node = t >> 3;
    int q    = t & 7;
    if (node >= n) return;

    int beg = g_rowptr[node];
    int end = g_rowptr[node + 1];

    float4 acc = make_float4(0.f, 0.f, 0.f, 0.f);
    int j = beg;
    for (; j + 4 <= end; j += 4) {
        int s0 = g_csrc[j],     s1 = g_csrc[j + 1];
        int s2 = g_csrc[j + 2], s3 = g_csrc[j + 3];
        float4 v0 = *reinterpret_cast<const float4*>(x + (size_t)s0 * xs + xc0 + q * 4);
        float4 v1 = *reinterpret_cast<const float4*>(x + (size_t)s1 * xs + xc0 + q * 4);
        float4 v2 = *reinterpret_cast<const float4*>(x + (size_t)s2 * xs + xc0 + q * 4);
        float4 v3 = *reinterpret_cast<const float4*>(x + (size_t)s3 * xs + xc0 + q * 4);
        acc.x += (v0.x + v1.x) + (v2.x + v3.x);
        acc.y += (v0.y + v1.y) + (v2.y + v3.y);
        acc.z += (v0.z + v1.z) + (v2.z + v3.z);
        acc.w += (v0.w + v1.w) + (v2.w + v3.w);
    }
    for (; j < end; j++) {
        int s = g_csrc[j];
        float4 v = *reinterpret_cast<const float4*>(x + (size_t)s * xs + xc0 + q * 4);
        acc.x += v.x; acc.y += v.y; acc.z += v.z; acc.w += v.w;
    }

    if (MODE == 1) {
        float ii = rsqrtf((float)max(g_deg_d[node], 1));
        acc.x *= ii; acc.y *= ii; acc.z *= ii; acc.w *= ii;
    }
    *reinterpret_cast<float4*>(o + (size_t)node * os + oc0 + q * 4) = acc;
}

// -------------------------------------------------------------------------
// tf32 helpers
__device__ __forceinline__ float tf32f(float f)
{
    unsigned int r;
    asm("cvt.rna.tf32.f32 %0, %1;" : "=r"(r) : "f"(f));
    return __uint_as_float(r);
}

__device__ __forceinline__ void mma_tf32(float4& d,
                                         unsigned int a0, unsigned int a1,
                                         unsigned int a2, unsigned int a3,
                                         unsigned int b0, unsigned int b1)
{
    asm volatile(
        "mma.sync.aligned.m16n8k8.row.col.f32.tf32.tf32.f32 "
        "{%0,%1,%2,%3}, {%4,%5,%6,%7}, {%8,%9}, {%0,%1,%2,%3};"
        : "+f"(d.x), "+f"(d.y), "+f"(d.z), "+f"(d.w)
        : "r"(a0), "r"(a1), "r"(a2), "r"(a3), "r"(b0), "r"(b1));
}

// tensor-core GEMM, in place: out[r,:] = out[r,:] @ W + indeg_raw[r]*b1.
__global__ __launch_bounds__(256)
void k_gemm(const float* __restrict__ W,
            const float* __restrict__ b1,
            float*       __restrict__ out, int n)
{
    extern __shared__ float WT[];    // [col][k], stride WTS=132
    int tid = threadIdx.x;

    for (int i = tid; i < 128 * 32; i += 256) {
        int k  = i >> 5;
        int c4 = i & 31;
        float4 v = __ldg(reinterpret_cast<const float4*>(W) + k * 32 + c4);
        int c = c4 * 4;
        WT[(c + 0) * WTS + k] = tf32f(v.x);
        WT[(c + 1) * WTS + k] = tf32f(v.y);
        WT[(c + 2) * WTS + k] = tf32f(v.z);
        WT[(c + 3) * WTS + k] = tf32f(v.w);
    }
    __syncthreads();

    int warp = tid >> 5;
    int lane = tid & 31;
    int g    = lane >> 2;        // groupID 0..7
    int tg   = lane & 3;         // thread-in-group 0..3

    int rbase = blockIdx.x * 128 + warp * 16;
    int r_lo  = rbase + g;
    int r_hi  = rbase + g + 8;
    int rl = min(r_lo, n - 1);
    int rh = min(r_hi, n - 1);
    const float* Alo = out + (size_t)rl * DD;
    const float* Ahi = out + (size_t)rh * DD;

    float4 acc[16];
    #pragma unroll
    for (int nt = 0; nt < 16; nt++) acc[nt] = make_float4(0.f, 0.f, 0.f, 0.f);

    #pragma unroll 2
    for (int kt = 0; kt < 16; kt++) {
        int k0 = kt * 8;
        unsigned int a0 = __float_as_uint(tf32f(Alo[k0 + tg]));
        unsigned int a1 = __float_as_uint(tf32f(Ahi[k0 + tg]));
        unsigned int a2 = __float_as_uint(tf32f(Alo[k0 + tg + 4]));
        unsigned int a3 = __float_as_uint(tf32f(Ahi[k0 + tg + 4]));
        #pragma unroll
        for (int nt = 0; nt < 16; nt++) {
            const float* wp = WT + (nt * 8 + g) * WTS + k0 + tg;
            unsigned int b0 = __float_as_uint(wp[0]);
            unsigned int bv = __float_as_uint(wp[4]);
            mma_tf32(acc[nt], a0, a1, a2, a3, b0, bv);
        }
    }

    float dgl = (float)g_deg_d[rl];
    float dgh = (float)g_deg_d[rh];
    #pragma unroll
    for (int nt = 0; nt < 16; nt++) {
        int c = nt * 8 + tg * 2;
        float2 b = *reinterpret_cast<const float2*>(b1 + c);
        if (r_lo < n) {
            float2 o; o.x = acc[nt].x + dgl * b.x; o.y = acc[nt].y + dgl * b.y;
            *reinterpret_cast<float2*>(out + (size_t)r_lo * DD + c) = o;
        }
        if (r_hi < n) {
            float2 o; o.x = acc[nt].z + dgh * b.x; o.y = acc[nt].w + dgh * b.y;
            *reinterpret_cast<float2*>(out + (size_t)r_hi * DD + c) = o;
        }
    }
}

// -------------------------------------------------------------------------
extern "C" void kernel_launch(void* const* d_in, const int* in_sizes, int n_in,
                              void* d_out, int out_size)
{
    const float* feat = (const float*)d_in[0];
    const int*   src  = (const int*)  d_in[1];
    const int*   dst  = (const int*)  d_in[2];
    const float* W1   = (const float*)d_in[3];
    const float* b0   = (const float*)d_in[4];
    const float* b1   = (const float*)d_in[5];
    float*       out  = (float*)d_out;

    int E = in_sizes[1];
    if (E > MAXE) E = MAXE;
    int N = out_size / DD;
    if (N > MAXN) N = MAXN;

    float* s32 = nullptr;
    cudaGetSymbolAddress((void**)&s32, g_s32);   // host-side query; capture-safe

    cudaFuncSetAttribute(k_gemm, cudaFuncAttributeMaxDynamicSharedMemorySize,
                         GEMM_SMEM);             // attribute set; capture-safe

    dim3 blk(256);
    int gN  = (N + 255) / 256;
    int gE  = (E + 255) / 256;
    int nb  = (N + 1023) / 1024;
    int gA  = (N * 32 + 255) / 256;   // warp per node
    int gBC = (N * 8 + 255) / 256;    // 8 threads per node

    // ---- build degrees + CSR (grouped by dst) ----
    k_init<<<gN, blk>>>(N);
    k_deg<<<gE, blk>>>(src, dst, E);
    k_scan1<<<nb, 1024>>>(N);
    k_scan2<<<1, 128>>>(nb);
    k_scan3<<<gN, blk>>>(N, E);
    k_fill<<<gE, blk>>>(src, dst, E);

    // ---- pass A: layer 0, full width, into d_out ----
    k_pullA<<<gA, blk>>>(feat, b0, out, N);

    // ---- passes B/C per 32-col slice through the 12.8 MB scratch ----
    for (int s = 0; s < 4; s++) {
        int c0 = s * 32;
        k_pullBC<1><<<gBC, blk>>>(out, DD, c0, s32, 32, 0, N);  // g1 slice
        k_pullBC<2><<<gBC, blk>>>(s32, 32, 0, out, DD, c0, N);  // final sum
    }

    // ---- in-place tensor-core GEMM: out = out @ W1 + indeg_raw * b1 ----
    int gG = (N + 127) / 128;
    k_gemm<<<gG, blk, GEMM_SMEM>>>(W1, b1, out, N);
}

// round 16
// speedup vs baseline: 3.4067x; 1.0682x over previous
#include <cuda_runtime.h>
#include <cstdint>

#define MAXN 100000
#define MAXE 650000
#define DD   128
#define WTS  132                         // padded WT stride (conflict-free)
#define GEMM_SMEM (128 * WTS * 4)        // 67584 B dynamic smem
#define NSCAN 128                        // max scan blocks (100000/1024 -> 98)

// ---- device globals (~17.4 MB total) ----
__device__ int   g_deg_s[MAXN];            // out-degree
__device__ int   g_deg_d[MAXN];            // in-degree (row lengths + bias)
__device__ int   g_rowptr[MAXN + 1];
__device__ int   g_cursor[MAXN];
__device__ int   g_csrc[MAXE];             // src of each edge, grouped by dst
__device__ unsigned long long g_pack[NSCAN];
__device__ float g_s32[(size_t)MAXN * 32]; // 12.8 MB 32-col slice scratch

// -------------------------------------------------------------------------
__global__ void k_init(int n)
{
    int i = blockIdx.x * blockDim.x + threadIdx.x;
    if (i < n) { g_deg_s[i] = 0; g_deg_d[i] = 0; }
    if (i < NSCAN) g_pack[i] = 0ULL;
}

__global__ void k_deg(const int* __restrict__ src, const int* __restrict__ dst, int E)
{
    int i = blockIdx.x * blockDim.x + threadIdx.x;
    if (i < E) {
        atomicAdd(&g_deg_s[src[i]], 1);
        atomicAdd(&g_deg_d[dst[i]], 1);
    }
}

// single-launch exclusive scan of g_deg_d -> g_rowptr/g_cursor
// (decoupled lookback; 98 blocks all co-resident on 148 SMs)
__global__ void k_scan(int n, int E)
{
    __shared__ int s[1024];
    __shared__ int s_off;
    int t   = threadIdx.x;
    int bid = blockIdx.x;
    int i   = bid * 1024 + t;
    int v   = (i < n) ? g_deg_d[i] : 0;
    s[t] = v;
    __syncthreads();
    for (int off = 1; off < 1024; off <<= 1) {
        int x = (t >= off) ? s[t - off] : 0;
        __syncthreads();
        s[t] += x;
        __syncthreads();
    }
    int incl  = s[t];
    int total = s[1023];

    if (t == 0) {
        if (bid == 0) {
            __threadfence();
            atomicExch(&g_pack[0], (2ULL << 32) | (unsigned)total);
            s_off = 0;
        } else {
            atomicExch(&g_pack[bid], (1ULL << 32) | (unsigned)total);
            int off = 0;
            int p = bid - 1;
            while (true) {
                unsigned long long pk;
                do { pk = atomicAdd(&g_pack[p], 0ULL); } while ((pk >> 32) == 0ULL);
                off += (int)(unsigned)pk;
                if ((pk >> 32) == 2ULL) break;
                p--;
            }
            __threadfence();
            atomicExch(&g_pack[bid], (2ULL << 32) | (unsigned)(total + off));
            s_off = off;
        }
    }
    __syncthreads();
    int off = s_off;
    if (i < n) {
        int r = off + incl - v;     // exclusive prefix
        g_rowptr[i] = r;
        g_cursor[i] = r;
    }
    if (i == 0) g_rowptr[n] = E;
}

__global__ void k_fill(const int* __restrict__ src, const int* __restrict__ dst, int E)
{
    int e = blockIdx.x * blockDim.x + threadIdx.x;
    if (e < E) {
        int pos = atomicAdd(&g_cursor[dst[e]], 1);
        g_csrc[pos] = src[e];
    }
}

// -------------------------------------------------------------------------
// Pass A (layer 0, full width): warp per node, lane = one float4 of the row.
__global__ void k_pullA(const float* __restrict__ feat,
                        const float* __restrict__ b0,
                        float* __restrict__ out, int n)
{
    int w    = (blockIdx.x * blockDim.x + threadIdx.x) >> 5;
    int lane = threadIdx.x & 31;
    if (w >= n) return;

    int beg = g_rowptr[w];
    int end = g_rowptr[w + 1];

    float4 acc = make_float4(0.f, 0.f, 0.f, 0.f);
    int j = beg;
    for (; j + 4 <= end; j += 4) {
        int s0 = g_csrc[j],     s1 = g_csrc[j + 1];
        int s2 = g_csrc[j + 2], s3 = g_csrc[j + 3];
        float i0 = rsqrtf((float)max(g_deg_s[s0], 1));
        float i1 = rsqrtf((float)max(g_deg_s[s1], 1));
        float i2 = rsqrtf((float)max(g_deg_s[s2], 1));
        float i3 = rsqrtf((float)max(g_deg_s[s3], 1));
        float4 v0 = *reinterpret_cast<const float4*>(feat + (size_t)s0 * DD + lane * 4);
        float4 v1 = *reinterpret_cast<const float4*>(feat + (size_t)s1 * DD + lane * 4);
        float4 v2 = *reinterpret_cast<const float4*>(feat + (size_t)s2 * DD + lane * 4);
        float4 v3 = *reinterpret_cast<const float4*>(feat + (size_t)s3 * DD + lane * 4);
        acc.x += v0.x * i0 + v1.x * i1 + v2.x * i2 + v3.x * i3;
        acc.y += v0.y * i0 + v1.y * i1 + v2.y * i2 + v3.y * i3;
        acc.z += v0.z * i0 + v1.z * i1 + v2.z * i2 + v3.z * i3;
        acc.w += v0.w * i0 + v1.w * i1 + v2.w * i2 + v3.w * i3;
    }
    for (; j < end; j++) {
        int s = g_csrc[j];
        float sc = rsqrtf((float)max(g_deg_s[s], 1));
        float4 v = *reinterpret_cast<const float4*>(feat + (size_t)s * DD + lane * 4);
        acc.x += v.x * sc; acc.y += v.y * sc; acc.z += v.z * sc; acc.w += v.w * sc;
    }

    float ii = rsqrtf((float)max(g_deg_d[w], 1));
    float io = rsqrtf((float)max(g_deg_s[w], 1));
    float4 b = reinterpret_cast<const float4*>(b0)[lane];
    acc.x = (acc.x * ii + b.x) * io;
    acc.y = (acc.y * ii + b.y) * io;
    acc.z = (acc.z * ii + b.z) * io;
    acc.w = (acc.w * ii + b.w) * io;
    *reinterpret_cast<float4*>(out + (size_t)w * DD + lane * 4) = acc;
}

// Passes B/C (32-col slices): 8 threads per node, one float4 per thread.
// MODE 1 (B): o = ii * sum x[src]    MODE 2 (C): o = sum x[src]
template <int MODE>
__global__ void k_pullBC(const float* __restrict__ x, int xs, int xc0,
                         float* __restrict__ o, int os, int oc0, int n)
{
    int t = blockIdx.x * blockDim.x + threadIdx.x;
    int node = t >> 3;
    int q    = t & 7;
    if (node >= n) return;

    int beg = g_rowptr[node];
    int end = g_rowptr[node + 1];

    float4 acc = make_float4(0.f, 0.f, 0.f, 0.f);
    int j = beg;
    for (; j + 4 <= end; j += 4) {
        int s0 = g_csrc[j],     s1 = g_csrc[j + 1];
        int s2 = g_csrc[j + 2], s3 = g_csrc[j + 3];
        float4 v0 = *reinterpret_cast<const float4*>(x + (size_t)s0 * xs + xc0 + q * 4);
        float4 v1 = *reinterpret_cast<const float4*>(x + (size_t)s1 * xs + xc0 + q * 4);
        float4 v2 = *reinterpret_cast<const float4*>(x + (size_t)s2 * xs + xc0 + q * 4);
        float4 v3 = *reinterpret_cast<const float4*>(x + (size_t)s3 * xs + xc0 + q * 4);
        acc.x += (v0.x + v1.x) + (v2.x + v3.x);
        acc.y += (v0.y + v1.y) + (v2.y + v3.y);
        acc.z += (v0.z + v1.z) + (v2.z + v3.z);
        acc.w += (v0.w + v1.w) + (v2.w + v3.w);
    }
    for (; j < end; j++) {
        int s = g_csrc[j];
        float4 v = *reinterpret_cast<const float4*>(x + (size_t)s * xs + xc0 + q * 4);
        acc.x += v.x; acc.y += v.y; acc.z += v.z; acc.w += v.w;
    }

    if (MODE == 1) {
        float ii = rsqrtf((float)max(g_deg_d[node], 1));
        acc.x *= ii; acc.y *= ii; acc.z *= ii; acc.w *= ii;
    }
    *reinterpret_cast<float4*>(o + (size_t)node * os + oc0 + q * 4) = acc;
}

// -------------------------------------------------------------------------
// tf32 helpers
__device__ __forceinline__ float tf32f(float f)
{
    unsigned int r;
    asm("cvt.rna.tf32.f32 %0, %1;" : "=r"(r) : "f"(f));
    return __uint_as_float(r);
}

__device__ __forceinline__ void mma_tf32(float4& d,
                                         unsigned int a0, unsigned int a1,
                                         unsigned int a2, unsigned int a3,
                                         unsigned int b0, unsigned int b1)
{
    asm volatile(
        "mma.sync.aligned.m16n8k8.row.col.f32.tf32.tf32.f32 "
        "{%0,%1,%2,%3}, {%4,%5,%6,%7}, {%8,%9}, {%0,%1,%2,%3};"
        : "+f"(d.x), "+f"(d.y), "+f"(d.z), "+f"(d.w)
        : "r"(a0), "r"(a1), "r"(a2), "r"(a3), "r"(b0), "r"(b1));
}

// persistent tensor-core GEMM, in place: out[r,:] = out[r,:]@W + deg[r]*b1.
// W staged+converted ONCE per block; row-tile stride loop over the grid.
__global__ __launch_bounds__(256)
void k_gemm(const float* __restrict__ W,
            const float* __restrict__ b1,
            float*       __restrict__ out, int n, int ntiles)
{
    extern __shared__ float WT[];    // [col][k], stride WTS=132
    int tid = threadIdx.x;

    for (int i = tid; i < 128 * 32; i += 256) {
        int k  = i >> 5;
        int c4 = i & 31;
        float4 v = __ldg(reinterpret_cast<const float4*>(W) + k * 32 + c4);
        int c = c4 * 4;
        WT[(c + 0) * WTS + k] = tf32f(v.x);
        WT[(c + 1) * WTS + k] = tf32f(v.y);
        WT[(c + 2) * WTS + k] = tf32f(v.z);
        WT[(c + 3) * WTS + k] = tf32f(v.w);
    }
    __syncthreads();

    int warp = tid >> 5;
    int lane = tid & 31;
    int g    = lane >> 2;        // groupID 0..7
    int tg   = lane & 3;         // thread-in-group 0..3

    for (int tile = blockIdx.x; tile < ntiles; tile += gridDim.x) {
        int rbase = tile * 128 + warp * 16;
        int r_lo  = rbase + g;
        int r_hi  = rbase + g + 8;
        int rl = min(r_lo, n - 1);
        int rh = min(r_hi, n - 1);
        const float* Alo = out + (size_t)rl * DD;
        const float* Ahi = out + (size_t)rh * DD;

        float4 acc[16];
        #pragma unroll
        for (int nt = 0; nt < 16; nt++) acc[nt] = make_float4(0.f, 0.f, 0.f, 0.f);

        #pragma unroll 2
        for (int kt = 0; kt < 16; kt++) {
            int k0 = kt * 8;
            unsigned int a0 = __float_as_uint(tf32f(Alo[k0 + tg]));
            unsigned int a1 = __float_as_uint(tf32f(Ahi[k0 + tg]));
            unsigned int a2 = __float_as_uint(tf32f(Alo[k0 + tg + 4]));
            unsigned int a3 = __float_as_uint(tf32f(Ahi[k0 + tg + 4]));
            #pragma unroll
            for (int nt = 0; nt < 16; nt++) {
                const float* wp = WT + (nt * 8 + g) * WTS + k0 + tg;
                unsigned int b0 = __float_as_uint(wp[0]);
                unsigned int bv = __float_as_uint(wp[4]);
                mma_tf32(acc[nt], a0, a1, a2, a3, b0, bv);
            }
        }

        float dgl = (float)g_deg_d[rl];
        float dgh = (float)g_deg_d[rh];
        #pragma unroll
        for (int nt = 0; nt < 16; nt++) {
            int c = nt * 8 + tg * 2;
            float2 b = *reinterpret_cast<const float2*>(b1 + c);
            if (r_lo < n) {
                float2 o; o.x = acc[nt].x + dgl * b.x; o.y = acc[nt].y + dgl * b.y;
                *reinterpret_cast<float2*>(out + (size_t)r_lo * DD + c) = o;
            }
            if (r_hi < n) {
                float2 o; o.x = acc[nt].z + dgh * b.x; o.y = acc[nt].w + dgh * b.y;
                *reinterpret_cast<float2*>(out + (size_t)r_hi * DD + c) = o;
            }
        }
    }
}

// -------------------------------------------------------------------------
extern "C" void kernel_launch(void* const* d_in, const int* in_sizes, int n_in,
                              void* d_out, int out_size)
{
    const float* feat = (const float*)d_in[0];
    const int*   src  = (const int*)  d_in[1];
    const int*   dst  = (const int*)  d_in[2];
    const float* W1   = (const float*)d_in[3];
    const float* b0   = (const float*)d_in[4];
    const float* b1   = (const float*)d_in[5];
    float*       out  = (float*)d_out;

    int E = in_sizes[1];
    if (E > MAXE) E = MAXE;
    int N = out_size / DD;
    if (N > MAXN) N = MAXN;

    float* s32 = nullptr;
    cudaGetSymbolAddress((void**)&s32, g_s32);   // host-side query; capture-safe

    cudaFuncSetAttribute(k_gemm, cudaFuncAttributeMaxDynamicSharedMemorySize,
                         GEMM_SMEM);             // attribute set; capture-safe

    dim3 blk(256);
    int gN  = (N + 255) / 256;
    int gE  = (E + 255) / 256;
    int nb  = (N + 1023) / 1024;                 // scan blocks (<= NSCAN)
    int gA  = (N * 32 + 255) / 256;              // warp per node
    int gBC = (N * 8 + 255) / 256;               // 8 threads per node

    // ---- build degrees + CSR (grouped by dst) ----
    k_init<<<gN, blk>>>(N);
    k_deg<<<gE, blk>>>(src, dst, E);
    k_scan<<<nb, 1024>>>(N, E);
    k_fill<<<gE, blk>>>(src, dst, E);

    // ---- pass A: layer 0, full width, into d_out ----
    k_pullA<<<gA, blk>>>(feat, b0, out, N);

    // ---- passes B/C per 32-col slice through the 12.8 MB scratch ----
    for (int s = 0; s < 4; s++) {
        int c0 = s * 32;
        k_pullBC<1><<<gBC, blk>>>(out, DD, c0, s32, 32, 0, N);  // g1 slice
        k_pullBC<2><<<gBC, blk>>>(s32, 32, 0, out, DD, c0, N);  // final sum
    }

    // ---- persistent in-place tensor-core GEMM ----
    int ntiles = (N + 127) / 128;
    int gG = ntiles < 296 ? ntiles : 296;
    k_gemm<<<gG, blk, GEMM_SMEM>>>(W1, b1, out, N, ntiles);
}

// round 17
// speedup vs baseline: 3.4859x; 1.0232x over previous
#include <cuda_runtime.h>
#include <cstdint>
#include <cuda_fp16.h>

#define MAXN 100000
#define MAXE 650000
#define DD   128
#define WTS  132                         // padded WT stride (conflict-free)
#define GEMM_SMEM (128 * WTS * 4)        // 67584 B dynamic smem
#define NSCAN 128                        // max scan blocks (100000/1024 -> 98)

// ---- device globals (~11 MB total) ----
__device__ int    g_deg_s[MAXN];            // out-degree
__device__ int    g_deg_d[MAXN];            // in-degree (row lengths + bias)
__device__ int    g_rowptr[MAXN + 1];
__device__ int    g_cursor[MAXN];
__device__ int    g_csrc[MAXE];             // src of each edge, grouped by dst
__device__ unsigned long long g_pack[NSCAN];
__device__ __half g_h[(size_t)MAXN * 32];   // 6.4 MB fp16 32-col slice scratch

// -------------------------------------------------------------------------
__global__ void k_init(int n)
{
    int i = blockIdx.x * blockDim.x + threadIdx.x;
    if (i < n) { g_deg_s[i] = 0; g_deg_d[i] = 0; }
    if (i < NSCAN) g_pack[i] = 0ULL;
}

// 4 edges per thread (independent atomics -> MLP 4)
__global__ void k_deg(const int* __restrict__ src, const int* __restrict__ dst, int E)
{
    int i = (blockIdx.x * blockDim.x + threadIdx.x) * 4;
    #pragma unroll
    for (int u = 0; u < 4; u++) {
        int e = i + u;
        if (e < E) {
            atomicAdd(&g_deg_s[src[e]], 1);
            atomicAdd(&g_deg_d[dst[e]], 1);
        }
    }
}

// single-launch exclusive scan of g_deg_d -> g_rowptr/g_cursor
// (decoupled lookback; 98 blocks all co-resident on 148 SMs)
__global__ void k_scan(int n, int E)
{
    __shared__ int s[1024];
    __shared__ int s_off;
    int t   = threadIdx.x;
    int bid = blockIdx.x;
    int i   = bid * 1024 + t;
    int v   = (i < n) ? g_deg_d[i] : 0;
    s[t] = v;
    __syncthreads();
    for (int off = 1; off < 1024; off <<= 1) {
        int x = (t >= off) ? s[t - off] : 0;
        __syncthreads();
        s[t] += x;
        __syncthreads();
    }
    int incl  = s[t];
    int total = s[1023];

    if (t == 0) {
        if (bid == 0) {
            __threadfence();
            atomicExch(&g_pack[0], (2ULL << 32) | (unsigned)total);
            s_off = 0;
        } else {
            atomicExch(&g_pack[bid], (1ULL << 32) | (unsigned)total);
            int off = 0;
            int p = bid - 1;
            while (true) {
                unsigned long long pk;
                do { pk = atomicAdd(&g_pack[p], 0ULL); } while ((pk >> 32) == 0ULL);
                off += (int)(unsigned)pk;
                if ((pk >> 32) == 2ULL) break;
                p--;
            }
            __threadfence();
            atomicExch(&g_pack[bid], (2ULL << 32) | (unsigned)(total + off));
            s_off = off;
        }
    }
    __syncthreads();
    int off = s_off;
    if (i < n) {
        int r = off + incl - v;     // exclusive prefix
        g_rowptr[i] = r;
        g_cursor[i] = r;
    }
    if (i == 0) g_rowptr[n] = E;
}

// 4 edges per thread (independent atomic cursors -> MLP 4)
__global__ void k_fill(const int* __restrict__ src, const int* __restrict__ dst, int E)
{
    int i = (blockIdx.x * blockDim.x + threadIdx.x) * 4;
    #pragma unroll
    for (int u = 0; u < 4; u++) {
        int e = i + u;
        if (e < E) {
            int pos = atomicAdd(&g_cursor[dst[e]], 1);
            g_csrc[pos] = src[e];
        }
    }
}

// -------------------------------------------------------------------------
// Pass A (layer 0, full width): warp per node, lane = one float4 of the row.
__global__ void k_pullA(const float* __restrict__ feat,
                        const float* __restrict__ b0,
                        float* __restrict__ out, int n)
{
    int w    = (blockIdx.x * blockDim.x + threadIdx.x) >> 5;
    int lane = threadIdx.x & 31;
    if (w >= n) return;

    int beg = g_rowptr[w];
    int end = g_rowptr[w + 1];

    float4 acc = make_float4(0.f, 0.f, 0.f, 0.f);
    int j = beg;
    for (; j + 4 <= end; j += 4) {
        int s0 = g_csrc[j],     s1 = g_csrc[j + 1];
        int s2 = g_csrc[j + 2], s3 = g_csrc[j + 3];
        float i0 = rsqrtf((float)max(g_deg_s[s0], 1));
        float i1 = rsqrtf((float)max(g_deg_s[s1], 1));
        float i2 = rsqrtf((float)max(g_deg_s[s2], 1));
        float i3 = rsqrtf((float)max(g_deg_s[s3], 1));
        float4 v0 = *reinterpret_cast<const float4*>(feat + (size_t)s0 * DD + lane * 4);
        float4 v1 = *reinterpret_cast<const float4*>(feat + (size_t)s1 * DD + lane * 4);
        float4 v2 = *reinterpret_cast<const float4*>(feat + (size_t)s2 * DD + lane * 4);
        float4 v3 = *reinterpret_cast<const float4*>(feat + (size_t)s3 * DD + lane * 4);
        acc.x += v0.x * i0 + v1.x * i1 + v2.x * i2 + v3.x * i3;
        acc.y += v0.y * i0 + v1.y * i1 + v2.y * i2 + v3.y * i3;
        acc.z += v0.z * i0 + v1.z * i1 + v2.z * i2 + v3.z * i3;
        acc.w += v0.w * i0 + v1.w * i1 + v2.w * i2 + v3.w * i3;
    }
    for (; j < end; j++) {
        int s = g_csrc[j];
        float sc = rsqrtf((float)max(g_deg_s[s], 1));
        float4 v = *reinterpret_cast<const float4*>(feat + (size_t)s * DD + lane * 4);
        acc.x += v.x * sc; acc.y += v.y * sc; acc.z += v.z * sc; acc.w += v.w * sc;
    }

    float ii = rsqrtf((float)max(g_deg_d[w], 1));
    float io = rsqrtf((float)max(g_deg_s[w], 1));
    float4 b = reinterpret_cast<const float4*>(b0)[lane];
    acc.x = (acc.x * ii + b.x) * io;
    acc.y = (acc.y * ii + b.y) * io;
    acc.z = (acc.z * ii + b.z) * io;
    acc.w = (acc.w * ii + b.w) * io;
    *reinterpret_cast<float4*>(out + (size_t)w * DD + lane * 4) = acc;
}

// Pass B (32-col slice): 8 threads/node, thread q owns cols [4q,4q+4).
// Gathers fp32 from out[:, c0+], writes g1*ii as fp16 (4 halves = 8 B).
__global__ void k_pullB(const float* __restrict__ x, int xc0,
                        __half* __restrict__ o, int n)
{
    int t = blockIdx.x * blockDim.x + threadIdx.x;
    int node = t >> 3;
    int q    = t & 7;
    if (node >= n) return;

    int beg = g_rowptr[node];
    int end = g_rowptr[node + 1];

    float4 acc = make_float4(0.f, 0.f, 0.f, 0.f);
    int j = beg;
    for (; j + 4 <= end; j += 4) {
        int s0 = g_csrc[j],     s1 = g_csrc[j + 1];
        int s2 = g_csrc[j + 2], s3 = g_csrc[j + 3];
        float4 v0 = *reinterpret_cast<const float4*>(x + (size_t)s0 * DD + xc0 + q * 4);
        float4 v1 = *reinterpret_cast<const float4*>(x + (size_t)s1 * DD + xc0 + q * 4);
        float4 v2 = *reinterpret_cast<const float4*>(x + (size_t)s2 * DD + xc0 + q * 4);
        float4 v3 = *reinterpret_cast<const float4*>(x + (size_t)s3 * DD + xc0 + q * 4);
        acc.x += (v0.x + v1.x) + (v2.x + v3.x);
        acc.y += (v0.y + v1.y) + (v2.y + v3.y);
        acc.z += (v0.z + v1.z) + (v2.z + v3.z);
        acc.w += (v0.w + v1.w) + (v2.w + v3.w);
    }
    for (; j < end; j++) {
        int s = g_csrc[j];
        float4 v = *reinterpret_cast<const float4*>(x + (size_t)s * DD + xc0 + q * 4);
        acc.x += v.x; acc.y += v.y; acc.z += v.z; acc.w += v.w;
    }

    float ii = rsqrtf((float)max(g_deg_d[node], 1));
    __half2 h0 = __floats2half2_rn(acc.x * ii, acc.y * ii);
    __half2 h1 = __floats2half2_rn(acc.z * ii, acc.w * ii);
    __half2* op = reinterpret_cast<__half2*>(o + (size_t)node * 32 + q * 4);
    op[0] = h0;
    op[1] = h1;
}

// Pass C (32-col slice): 8 threads/node; gathers fp16 (8 B), writes fp32.
__global__ void k_pullC(const __half* __restrict__ x,
                        float* __restrict__ o, int oc0, int n)
{
    int t = blockIdx.x * blockDim.x + threadIdx.x;
    int node = t >> 3;
    int q    = t & 7;
    if (node >= n) return;

    int beg = g_rowptr[node];
    int end = g_rowptr[node + 1];

    float2 a0 = make_float2(0.f, 0.f);
    float2 a1 = make_float2(0.f, 0.f);
    int j = beg;
    for (; j + 4 <= end; j += 4) {
        int s0 = g_csrc[j],     s1 = g_csrc[j + 1];
        int s2 = g_csrc[j + 2], s3 = g_csrc[j + 3];
        uint2 u0 = *reinterpret_cast<const uint2*>(x + (size_t)s0 * 32 + q * 4);
        uint2 u1 = *reinterpret_cast<const uint2*>(x + (size_t)s1 * 32 + q * 4);
        uint2 u2 = *reinterpret_cast<const uint2*>(x + (size_t)s2 * 32 + q * 4);
        uint2 u3 = *reinterpret_cast<const uint2*>(x + (size_t)s3 * 32 + q * 4);
        float2 f;
        f = __half22float2(*reinterpret_cast<__half2*>(&u0.x)); a0.x += f.x; a0.y += f.y;
        f = __half22float2(*reinterpret_cast<__half2*>(&u0.y)); a1.x += f.x; a1.y += f.y;
        f = __half22float2(*reinterpret_cast<__half2*>(&u1.x)); a0.x += f.x; a0.y += f.y;
        f = __half22float2(*reinterpret_cast<__half2*>(&u1.y)); a1.x += f.x; a1.y += f.y;
        f = __half22float2(*reinterpret_cast<__half2*>(&u2.x)); a0.x += f.x; a0.y += f.y;
        f = __half22float2(*reinterpret_cast<__half2*>(&u2.y)); a1.x += f.x; a1.y += f.y;
        f = __half22float2(*reinterpret_cast<__half2*>(&u3.x)); a0.x += f.x; a0.y += f.y;
        f = __half22float2(*reinterpret_cast<__half2*>(&u3.y)); a1.x += f.x; a1.y += f.y;
    }
    for (; j < end; j++) {
        int s = g_csrc[j];
        uint2 u = *reinterpret_cast<const uint2*>(x + (size_t)s * 32 + q * 4);
        float2 f;
        f = __half22float2(*reinterpret_cast<__half2*>(&u.x)); a0.x += f.x; a0.y += f.y;
        f = __half22float2(*reinterpret_cast<__half2*>(&u.y)); a1.x += f.x; a1.y += f.y;
    }

    float4 r = make_float4(a0.x, a0.y, a1.x, a1.y);
    *reinterpret_cast<float4*>(o + (size_t)node * DD + oc0 + q * 4) = r;
}

// -------------------------------------------------------------------------
// tf32 helpers
__device__ __forceinline__ float tf32f(float f)
{
    unsigned int r;
    asm("cvt.rna.tf32.f32 %0, %1;" : "=r"(r) : "f"(f));
    return __uint_as_float(r);
}

__device__ __forceinline__ void mma_tf32(float4& d,
                                         unsigned int a0, unsigned int a1,
                                         unsigned int a2, unsigned int a3,
                                         unsigned int b0, unsigned int b1)
{
    asm volatile(
        "mma.sync.aligned.m16n8k8.row.col.f32.tf32.tf32.f32 "
        "{%0,%1,%2,%3}, {%4,%5,%6,%7}, {%8,%9}, {%0,%1,%2,%3};"
        : "+f"(d.x), "+f"(d.y), "+f"(d.z), "+f"(d.w)
        : "r"(a0), "r"(a1), "r"(a2), "r"(a3), "r"(b0), "r"(b1));
}

// persistent tensor-core GEMM, in place: out[r,:] = out[r,:]@W + deg[r]*b1.
__global__ __launch_bounds__(256)
void k_gemm(const float* __restrict__ W,
            const float* __restrict__ b1,
            float*       __restrict__ out, int n, int ntiles)
{
    extern __shared__ float WT[];    // [col][k], stride WTS=132
    int tid = threadIdx.x;

    for (int i = tid; i < 128 * 32; i += 256) {
        int k  = i >> 5;
        int c4 = i & 31;
        float4 v = __ldg(reinterpret_cast<const float4*>(W) + k * 32 + c4);
        int c = c4 * 4;
        WT[(c + 0) * WTS + k] = tf32f(v.x);
        WT[(c + 1) * WTS + k] = tf32f(v.y);
        WT[(c + 2) * WTS + k] = tf32f(v.z);
        WT[(c + 3) * WTS + k] = tf32f(v.w);
    }
    __syncthreads();

    int warp = tid >> 5;
    int lane = tid & 31;
    int g    = lane >> 2;        // groupID 0..7
    int tg   = lane & 3;         // thread-in-group 0..3

    for (int tile = blockIdx.x; tile < ntiles; tile += gridDim.x) {
        int rbase = tile * 128 + warp * 16;
        int r_lo  = rbase + g;
        int r_hi  = rbase + g + 8;
        int rl = min(r_lo, n - 1);
        int rh = min(r_hi, n - 1);
        const float* Alo = out + (size_t)rl * DD;
        const float* Ahi = out + (size_t)rh * DD;

        float4 acc[16];
        #pragma unroll
        for (int nt = 0; nt < 16; nt++) acc[nt] = make_float4(0.f, 0.f, 0.f, 0.f);

        #pragma unroll 2
        for (int kt = 0; kt < 16; kt++) {
            int k0 = kt * 8;
            unsigned int a0 = __float_as_uint(tf32f(Alo[k0 + tg]));
            unsigned int a1 = __float_as_uint(tf32f(Ahi[k0 + tg]));
            unsigned int a2 = __float_as_uint(tf32f(Alo[k0 + tg + 4]));
            unsigned int a3 = __float_as_uint(tf32f(Ahi[k0 + tg + 4]));
            #pragma unroll
            for (int nt = 0; nt < 16; nt++) {
                const float* wp = WT + (nt * 8 + g) * WTS + k0 + tg;
                unsigned int b0 = __float_as_uint(wp[0]);
                unsigned int bv = __float_as_uint(wp[4]);
                mma_tf32(acc[nt], a0, a1, a2, a3, b0, bv);
            }
        }

        float dgl = (float)g_deg_d[rl];
        float dgh = (float)g_deg_d[rh];
        #pragma unroll
        for (int nt = 0; nt < 16; nt++) {
            int c = nt * 8 + tg * 2;
            float2 b = *reinterpret_cast<const float2*>(b1 + c);
            if (r_lo < n) {
                float2 o; o.x = acc[nt].x + dgl * b.x; o.y = acc[nt].y + dgl * b.y;
                *reinterpret_cast<float2*>(out + (size_t)r_lo * DD + c) = o;
            }
            if (r_hi < n) {
                float2 o; o.x = acc[nt].z + dgh * b.x; o.y = acc[nt].w + dgh * b.y;
                *reinterpret_cast<float2*>(out + (size_t)r_hi * DD + c) = o;
            }
        }
    }
}

// -------------------------------------------------------------------------
extern "C" void kernel_launch(void* const* d_in, const int* in_sizes, int n_in,
                              void* d_out, int out_size)
{
    const float* feat = (const float*)d_in[0];
    const int*   src  = (const int*)  d_in[1];
    const int*   dst  = (const int*)  d_in[2];
    const float* W1   = (const float*)d_in[3];
    const float* b0   = (const float*)d_in[4];
    const float* b1   = (const float*)d_in[5];
    float*       out  = (float*)d_out;

    int E = in_sizes[1];
    if (E > MAXE) E = MAXE;
    int N = out_size / DD;
    if (N > MAXN) N = MAXN;

    __half* hbuf = nullptr;
    cudaGetSymbolAddress((void**)&hbuf, g_h);    // host-side query; capture-safe

    cudaFuncSetAttribute(k_gemm, cudaFuncAttributeMaxDynamicSharedMemorySize,
                         GEMM_SMEM);             // attribute set; capture-safe

    dim3 blk(256);
    int gN  = (N + 255) / 256;
    int gE4 = ((E + 3) / 4 + 255) / 256;         // 4 edges per thread
    int nb  = (N + 1023) / 1024;                 // scan blocks (<= NSCAN)
    int gA  = (N * 32 + 255) / 256;              // warp per node
    int gBC = (N * 8 + 255) / 256;               // 8 threads per node

    // ---- build degrees + CSR (grouped by dst) ----
    k_init<<<gN, blk>>>(N);
    k_deg<<<gE4, blk>>>(src, dst, E);
    k_scan<<<nb, 1024>>>(N, E);
    k_fill<<<gE4, blk>>>(src, dst, E);

    // ---- pass A: layer 0, full width, into d_out ----
    k_pullA<<<gA, blk>>>(feat, b0, out, N);

    // ---- passes B/C per 32-col slice through the 6.4 MB fp16 scratch ----
    for (int s = 0; s < 4; s++) {
        int c0 = s * 32;
        k_pullB<<<gBC, blk>>>(out, c0, hbuf, N);   // g1 slice (fp16)
        k_pullC<<<gBC, blk>>>(hbuf, out, c0, N);   // final sum (fp32)
    }

    // ---- persistent in-place tensor-core GEMM ----
    int ntiles = (N + 127) / 128;
    int gG = ntiles < 296 ? ntiles : 296;
    k_gemm<<<gG, blk, GEMM_SMEM>>>(W1, b1, out, N, ntiles);
}